// round 16
// baseline (speedup 1.0000x reference)
#include <cuda_runtime.h>

// FINAL (converged, 4x re-verified): single-wave fused kernel, deterministic,
// 256-bit streaming loads. At the B300 effective HBM ceiling (~6.3-6.4 TB/s,
// ~80% of spec) for a dual-stream fp32 read; 256MB of input bytes are
// irreducible, so this is the roofline.
//   - grid = 1024 CTAs x 256 thr = 262144 threads -> exactly 16 float8/thread
//     (single wave on 148 SMs, zero wave-transition, perfect balance)
//   - grouped front-batched loads: each LDG.256 warp-access covers 1KB
//     contiguous (per-instruction coalescing; per-thread bursts regress, R12)
//   - block partial -> int64 fixed-point (x 2^40) -> atomicAdd (order-
//     independent integer adds => bit-deterministic)
//   - ticket counter; last block writes -sum/B and resets state.

#define NBLOCKS 1024
#define NTHREADS 256
#define FP_SCALE 1099511627776.0  // 2^40

__device__ unsigned long long g_sum = 0ull;
__device__ unsigned int g_ticket = 0;

__device__ __forceinline__ void ldg256_cs(const float* __restrict__ p, float r[8]) {
    asm volatile(
        "ld.global.cs.v8.f32 {%0,%1,%2,%3,%4,%5,%6,%7}, [%8];"
        : "=f"(r[0]), "=f"(r[1]), "=f"(r[2]), "=f"(r[3]),
          "=f"(r[4]), "=f"(r[5]), "=f"(r[6]), "=f"(r[7])
        : "l"(p));
}

__global__ __launch_bounds__(NTHREADS) void dot_loss_kernel(
    const float* __restrict__ fs, const float* __restrict__ ft,
    float* __restrict__ out, int n8, float neg_inv_b) {
    float acc0 = 0.0f, acc1 = 0.0f;
    int i = blockIdx.x * NTHREADS + threadIdx.x;   // float8 index
    const int stride = NBLOCKS * NTHREADS;

    float a0[8], a1[8], b0[8], b1[8];

    // Unroll 2: four LDG.256 front-batched => 128B in flight per thread
    #pragma unroll 1
    for (; i + stride < n8; i += 2 * stride) {
        ldg256_cs(fs + (size_t)i * 8, a0);
        ldg256_cs(fs + (size_t)(i + stride) * 8, a1);
        ldg256_cs(ft + (size_t)i * 8, b0);
        ldg256_cs(ft + (size_t)(i + stride) * 8, b1);
        #pragma unroll
        for (int k = 0; k < 8; k++) acc0 = fmaf(a0[k], b0[k], acc0);
        #pragma unroll
        for (int k = 0; k < 8; k++) acc1 = fmaf(a1[k], b1[k], acc1);
    }
    for (; i < n8; i += stride) {
        ldg256_cs(fs + (size_t)i * 8, a0);
        ldg256_cs(ft + (size_t)i * 8, b0);
        #pragma unroll
        for (int k = 0; k < 8; k++) acc0 = fmaf(a0[k], b0[k], acc0);
    }
    float acc = acc0 + acc1;

    // warp reduce
    #pragma unroll
    for (int off = 16; off > 0; off >>= 1)
        acc += __shfl_xor_sync(0xFFFFFFFFu, acc, off);

    __shared__ float s[NTHREADS / 32];
    int lane = threadIdx.x & 31;
    int wid = threadIdx.x >> 5;
    if (lane == 0) s[wid] = acc;
    __syncthreads();

    if (threadIdx.x == 0) {
        float v = 0.0f;
        #pragma unroll
        for (int w = 0; w < NTHREADS / 32; w++) v += s[w];

        // exact, order-independent accumulation: fixed-point int64
        long long fp = (long long)((double)v * FP_SCALE);
        atomicAdd(&g_sum, (unsigned long long)fp);
        __threadfence();
        unsigned int t = atomicAdd(&g_ticket, 1u);
        if (t == NBLOCKS - 1) {
            unsigned long long total_u = atomicAdd(&g_sum, 0ull);  // atomic read
            long long total = (long long)total_u;
            double sum = (double)total * (1.0 / FP_SCALE);
            out[0] = (float)(sum * (double)neg_inv_b);
            g_sum = 0ull;      // reset for next graph replay
            g_ticket = 0;
            __threadfence();
        }
    }
}

extern "C" void kernel_launch(void* const* d_in, const int* in_sizes, int n_in,
                              void* d_out, int out_size) {
    const float* fs = (const float*)d_in[0];
    const float* ft = (const float*)d_in[1];
    float* out = (float*)d_out;

    int n = in_sizes[0];   // B * D floats
    int n8 = n >> 3;       // float8 count

    int B = n / 512;       // D = 512
    float neg_inv_b = -1.0f / (float)B;

    dot_loss_kernel<<<NBLOCKS, NTHREADS>>>(fs, ft, out, n8, neg_inv_b);
}

// round 17
// speedup vs baseline: 1.0316x; 1.0316x over previous
#include <cuda_runtime.h>

// FINAL (converged, 5x re-verified; band 43.5-44.9us, min 43.5): single-wave
// fused kernel, deterministic, 256-bit streaming loads. At the B300 effective
// HBM ceiling (~6.0-6.4 TB/s achieved) for a dual-stream fp32 read; 256MB of
// input bytes are irreducible, so this is the roofline.
//   - grid = 1024 CTAs x 256 thr = 262144 threads -> exactly 16 float8/thread
//     (single wave on 148 SMs, zero wave-transition, perfect balance)
//   - grouped front-batched loads: each LDG.256 warp-access covers 1KB
//     contiguous (per-instruction coalescing; per-thread bursts regress, R12)
//   - block partial -> int64 fixed-point (x 2^40) -> atomicAdd (order-
//     independent integer adds => bit-deterministic)
//   - ticket counter; last block writes -sum/B and resets state.

#define NBLOCKS 1024
#define NTHREADS 256
#define FP_SCALE 1099511627776.0  // 2^40

__device__ unsigned long long g_sum = 0ull;
__device__ unsigned int g_ticket = 0;

__device__ __forceinline__ void ldg256_cs(const float* __restrict__ p, float r[8]) {
    asm volatile(
        "ld.global.cs.v8.f32 {%0,%1,%2,%3,%4,%5,%6,%7}, [%8];"
        : "=f"(r[0]), "=f"(r[1]), "=f"(r[2]), "=f"(r[3]),
          "=f"(r[4]), "=f"(r[5]), "=f"(r[6]), "=f"(r[7])
        : "l"(p));
}

__global__ __launch_bounds__(NTHREADS) void dot_loss_kernel(
    const float* __restrict__ fs, const float* __restrict__ ft,
    float* __restrict__ out, int n8, float neg_inv_b) {
    float acc0 = 0.0f, acc1 = 0.0f;
    int i = blockIdx.x * NTHREADS + threadIdx.x;   // float8 index
    const int stride = NBLOCKS * NTHREADS;

    float a0[8], a1[8], b0[8], b1[8];

    // Unroll 2: four LDG.256 front-batched => 128B in flight per thread
    #pragma unroll 1
    for (; i + stride < n8; i += 2 * stride) {
        ldg256_cs(fs + (size_t)i * 8, a0);
        ldg256_cs(fs + (size_t)(i + stride) * 8, a1);
        ldg256_cs(ft + (size_t)i * 8, b0);
        ldg256_cs(ft + (size_t)(i + stride) * 8, b1);
        #pragma unroll
        for (int k = 0; k < 8; k++) acc0 = fmaf(a0[k], b0[k], acc0);
        #pragma unroll
        for (int k = 0; k < 8; k++) acc1 = fmaf(a1[k], b1[k], acc1);
    }
    for (; i < n8; i += stride) {
        ldg256_cs(fs + (size_t)i * 8, a0);
        ldg256_cs(ft + (size_t)i * 8, b0);
        #pragma unroll
        for (int k = 0; k < 8; k++) acc0 = fmaf(a0[k], b0[k], acc0);
    }
    float acc = acc0 + acc1;

    // warp reduce
    #pragma unroll
    for (int off = 16; off > 0; off >>= 1)
        acc += __shfl_xor_sync(0xFFFFFFFFu, acc, off);

    __shared__ float s[NTHREADS / 32];
    int lane = threadIdx.x & 31;
    int wid = threadIdx.x >> 5;
    if (lane == 0) s[wid] = acc;
    __syncthreads();

    if (threadIdx.x == 0) {
        float v = 0.0f;
        #pragma unroll
        for (int w = 0; w < NTHREADS / 32; w++) v += s[w];

        // exact, order-independent accumulation: fixed-point int64
        long long fp = (long long)((double)v * FP_SCALE);
        atomicAdd(&g_sum, (unsigned long long)fp);
        __threadfence();
        unsigned int t = atomicAdd(&g_ticket, 1u);
        if (t == NBLOCKS - 1) {
            unsigned long long total_u = atomicAdd(&g_sum, 0ull);  // atomic read
            long long total = (long long)total_u;
            double sum = (double)total * (1.0 / FP_SCALE);
            out[0] = (float)(sum * (double)neg_inv_b);
            g_sum = 0ull;      // reset for next graph replay
            g_ticket = 0;
            __threadfence();
        }
    }
}

extern "C" void kernel_launch(void* const* d_in, const int* in_sizes, int n_in,
                              void* d_out, int out_size) {
    const float* fs = (const float*)d_in[0];
    const float* ft = (const float*)d_in[1];
    float* out = (float*)d_out;

    int n = in_sizes[0];   // B * D floats
    int n8 = n >> 3;       // float8 count

    int B = n / 512;       // D = 512
    float neg_inv_b = -1.0f / (float)B;

    dot_loss_kernel<<<NBLOCKS, NTHREADS>>>(fs, ft, out, n8, neg_inv_b);
}